// round 3
// baseline (speedup 1.0000x reference)
#include <cuda_runtime.h>
#include <math.h>

#define B 4096
#define D 128
#define NT 32              // 4096 / 128 tiles per dimension
#define NCLS 64

// ---- scratch (device globals; no allocation allowed) ----
__device__ float  g_rowneg[B];
__device__ float  g_mag[B];
__device__ int    g_t32[B];
__device__ int    g_hist[NCLS];
__device__ int    g_cls_off[NCLS + 1];
__device__ int    g_cursor[NCLS];
__device__ int    g_cls_idx[B];
__device__ double g_loss;

// ---------------------------------------------------------------------------
// K0: zero accumulators (graph replays: must reset every launch)
// ---------------------------------------------------------------------------
__global__ void k_init() {
    int idx = blockIdx.x * blockDim.x + threadIdx.x;
    if (idx < B)    g_rowneg[idx] = 0.f;
    if (idx < NCLS) { g_hist[idx] = 0; g_cursor[idx] = 0; }
    if (idx == 0)   g_loss = 0.0;
}

// ---------------------------------------------------------------------------
// K1: per-row squared magnitude + int32 labels + label histogram
// ---------------------------------------------------------------------------
__global__ void __launch_bounds__(256) k_mag(const float* __restrict__ X,
                                             const int* __restrict__ T) {
    int warp = threadIdx.x >> 5;
    int lane = threadIdx.x & 31;
    int row  = blockIdx.x * 8 + warp;
    const float4* xr = (const float4*)(X + (size_t)row * D);
    float4 v = xr[lane];
    float s = v.x * v.x + v.y * v.y + v.z * v.z + v.w * v.w;
    #pragma unroll
    for (int off = 16; off; off >>= 1) s += __shfl_xor_sync(0xffffffff, s, off);
    if (lane == 0) {
        g_mag[row] = s;
        int t = T[row] & (NCLS - 1);
        g_t32[row] = t;
        atomicAdd(&g_hist[t], 1);
    }
}

// ---------------------------------------------------------------------------
// K1b: exclusive prefix of histogram (tiny, 1 thread is fine)
// ---------------------------------------------------------------------------
__global__ void k_prefix() {
    if (threadIdx.x == 0) {
        int acc = 0;
        #pragma unroll
        for (int c = 0; c < NCLS; c++) { g_cls_off[c] = acc; acc += g_hist[c]; }
        g_cls_off[NCLS] = acc;
    }
}

// ---------------------------------------------------------------------------
// K1c: scatter indices into class buckets
// ---------------------------------------------------------------------------
__global__ void __launch_bounds__(256) k_scatter() {
    int i = blockIdx.x * 256 + threadIdx.x;
    int c = g_t32[i];
    int pos = atomicAdd(&g_cursor[c], 1);
    g_cls_idx[g_cls_off[c] + pos] = i;
}

// ---------------------------------------------------------------------------
// K2: symmetric tiled dist GEMM + fused masked-exp row/col reduction
//   128x128 tile / block, 256 threads, 8x8 register blocking,
//   K chunked 4x32, smem transposed [k][m]. Upper-triangle tiles only.
//   No dist matrix stored — pass 2 recomputes per positive pair.
// ---------------------------------------------------------------------------
__global__ void __launch_bounds__(256) k_dist(const float* __restrict__ X) {
    __shared__ float As[32][128];
    __shared__ float Bs[32][128];
    __shared__ float rbuf[128];
    __shared__ float cbuf[128];

    int tid = threadIdx.x;

    int idx = blockIdx.x;
    int bi = 0, rem = idx;
    while (rem >= NT - bi) { rem -= NT - bi; bi++; }
    int bj = bi + rem;

    int tx = tid & 15, ty = tid >> 4;

    float acc[8][8];
    #pragma unroll
    for (int ii = 0; ii < 8; ii++)
        #pragma unroll
        for (int jj = 0; jj < 8; jj++) acc[ii][jj] = 0.f;

    const float4* Xv = (const float4*)X;

    for (int c = 0; c < 4; ++c) {          // K chunks of 32
        #pragma unroll
        for (int f = 0; f < 4; f++) {
            int e  = tid + 256 * f;        // 0..1023
            int r  = e & 127;
            int kc = e >> 7;               // float4 chunk within K-32 (0..7)
            float4 va = Xv[(size_t)(bi * 128 + r) * 32 + c * 8 + kc];
            float4 vb = Xv[(size_t)(bj * 128 + r) * 32 + c * 8 + kc];
            As[kc * 4 + 0][r] = va.x; As[kc * 4 + 1][r] = va.y;
            As[kc * 4 + 2][r] = va.z; As[kc * 4 + 3][r] = va.w;
            Bs[kc * 4 + 0][r] = vb.x; Bs[kc * 4 + 1][r] = vb.y;
            Bs[kc * 4 + 2][r] = vb.z; Bs[kc * 4 + 3][r] = vb.w;
        }
        __syncthreads();

        #pragma unroll 8
        for (int kk = 0; kk < 32; ++kk) {
            float4 a0 = *(const float4*)&As[kk][ty * 8];
            float4 a1 = *(const float4*)&As[kk][ty * 8 + 4];
            float4 b0 = *(const float4*)&Bs[kk][tx * 8];
            float4 b1 = *(const float4*)&Bs[kk][tx * 8 + 4];
            float a[8] = {a0.x, a0.y, a0.z, a0.w, a1.x, a1.y, a1.z, a1.w};
            float b[8] = {b0.x, b0.y, b0.z, b0.w, b1.x, b1.y, b1.z, b1.w};
            #pragma unroll
            for (int ii = 0; ii < 8; ii++)
                #pragma unroll
                for (int jj = 0; jj < 8; jj++)
                    acc[ii][jj] += a[ii] * b[jj];
        }
        __syncthreads();
    }

    // --- epilogue: masked exp(1-dist), row + col partial sums ---
    int i0 = bi * 128, j0 = bj * 128;
    float magi[8], magj[8];
    int   ti[8], tj[8];
    #pragma unroll
    for (int ii = 0; ii < 8; ii++) {
        int gi = i0 + ty * 8 + ii;
        magi[ii] = g_mag[gi]; ti[ii] = g_t32[gi];
    }
    #pragma unroll
    for (int jj = 0; jj < 8; jj++) {
        int gj = j0 + tx * 8 + jj;
        magj[jj] = g_mag[gj]; tj[jj] = g_t32[gj];
    }

    float rowsum[8] = {0, 0, 0, 0, 0, 0, 0, 0};
    float colsum[8] = {0, 0, 0, 0, 0, 0, 0, 0};

    #pragma unroll
    for (int ii = 0; ii < 8; ii++) {
        #pragma unroll
        for (int jj = 0; jj < 8; jj++) {
            float d2 = magi[ii] + magj[jj] - 2.f * acc[ii][jj];
            float dist = d2 > 0.f ? sqrtf(d2) : 0.f;
            float e = (ti[ii] != tj[jj]) ? __expf(1.0f - dist) : 0.f;
            rowsum[ii] += e;
            colsum[jj] += e;
        }
    }

    #pragma unroll
    for (int ii = 0; ii < 8; ii++) {
        #pragma unroll
        for (int off = 1; off < 16; off <<= 1)
            rowsum[ii] += __shfl_xor_sync(0xffffffff, rowsum[ii], off);
    }
    #pragma unroll
    for (int jj = 0; jj < 8; jj++)
        colsum[jj] += __shfl_xor_sync(0xffffffff, colsum[jj], 16);

    if (tid < 128) { rbuf[tid] = 0.f; cbuf[tid] = 0.f; }
    __syncthreads();

    if (tx == 0) {
        #pragma unroll
        for (int ii = 0; ii < 8; ii++)
            atomicAdd(&rbuf[ty * 8 + ii], rowsum[ii]);
    }
    if ((ty & 1) == 0) {
        #pragma unroll
        for (int jj = 0; jj < 8; jj++)
            atomicAdd(&cbuf[tx * 8 + jj], colsum[jj]);
    }
    __syncthreads();

    if (tid < 128) {
        atomicAdd(&g_rowneg[i0 + tid], rbuf[tid]);
        if (bi != bj)
            atomicAdd(&g_rowneg[j0 + tid], cbuf[tid]);
    }
}

// ---------------------------------------------------------------------------
// K3: positive pairs only — one block per class, one warp per pair.
//   Recompute dist from X (L2-resident); hinge^2 accumulate.
// ---------------------------------------------------------------------------
__global__ void __launch_bounds__(256) k_loss(const float* __restrict__ X) {
    int c   = blockIdx.x;
    int off = g_cls_off[c];
    int n   = g_cls_off[c + 1] - off;
    long P  = (long)n * (n - 1) / 2;

    int warp = threadIdx.x >> 5;
    int lane = threadIdx.x & 31;

    float wsum = 0.f;
    for (long p = warp; p < P; p += 8) {
        // decode triangular index p -> (u, v), 0 <= v < u < n
        int u = (int)((1.0f + sqrtf(8.0f * (float)p + 1.0f)) * 0.5f);
        while ((long)u * (u - 1) / 2 > p) u--;
        while ((long)(u + 1) * u / 2 <= p) u++;
        int v = (int)(p - (long)u * (u - 1) / 2);

        int a = g_cls_idx[off + u];
        int b = g_cls_idx[off + v];

        const float4* xa = (const float4*)(X + (size_t)a * D);
        const float4* xb = (const float4*)(X + (size_t)b * D);
        float4 va = xa[lane], vb = xb[lane];
        float s = va.x * vb.x + va.y * vb.y + va.z * vb.z + va.w * vb.w;
        #pragma unroll
        for (int o = 16; o; o >>= 1) s += __shfl_xor_sync(0xffffffff, s, o);

        float d2 = g_mag[a] + g_mag[b] - 2.f * s;
        float dist = d2 > 0.f ? sqrtf(d2) : 0.f;
        float l = logf(g_rowneg[a] + g_rowneg[b]) + dist;
        if (l > 0.f) wsum += l * l;
    }

    if (lane == 0 && wsum != 0.f) atomicAdd(&g_loss, (double)wsum);
}

// ---------------------------------------------------------------------------
// K4: counter = sum_c n_c*(n_c-1)/2 ; out = loss / (2*counter)
// ---------------------------------------------------------------------------
__global__ void k_final(float* __restrict__ out) {
    __shared__ long long cnt[NCLS];
    int t = threadIdx.x;
    long long n = (long long)g_hist[t];
    cnt[t] = n * (n - 1) / 2;
    __syncthreads();
    if (t == 0) {
        long long total = 0;
        #pragma unroll
        for (int c = 0; c < NCLS; c++) total += cnt[c];
        out[0] = (float)(g_loss / (2.0 * (double)total));
    }
}

// ---------------------------------------------------------------------------
extern "C" void kernel_launch(void* const* d_in, const int* in_sizes, int n_in,
                              void* d_out, int out_size) {
    const float* X   = (const float*)d_in[0];
    const int*   T   = (const int*)d_in[1];      // int32: JAX x64 disabled
    float*       out = (float*)d_out;

    k_init<<<16, 256>>>();
    k_mag<<<B / 8, 256>>>(X, T);
    k_prefix<<<1, 32>>>();
    k_scatter<<<B / 256, 256>>>();
    k_dist<<<NT * (NT + 1) / 2, 256>>>(X);
    k_loss<<<NCLS, 256>>>(X);
    k_final<<<1, NCLS>>>(out);
}

// round 4
// speedup vs baseline: 3.2456x; 3.2456x over previous
#include <cuda_runtime.h>
#include <math.h>

#define B 4096
#define D 128
#define NT 32              // 4096 / 128 tiles per dimension
#define NCLS 64
#define PB 2048            // per-block positive-pair buffer (expected ~256)
#define PAIR_CAP (1 << 20) // global pair capacity (expected ~131K)

// ---- scratch (device globals; no allocation allowed) ----
__device__ float    g_rowneg[B];
__device__ float    g_mag[B];
__device__ int      g_t32[B];
__device__ int      g_hist[NCLS];
__device__ int      g_npairs;
__device__ float    g_pair_d[PAIR_CAP];
__device__ unsigned g_pair_ij[PAIR_CAP];
__device__ double   g_loss;

// ---------------------------------------------------------------------------
// K0: zero accumulators (graph replays: must reset every launch)
// ---------------------------------------------------------------------------
__global__ void k_init() {
    int idx = blockIdx.x * blockDim.x + threadIdx.x;
    if (idx < B)    g_rowneg[idx] = 0.f;
    if (idx < NCLS) g_hist[idx] = 0;
    if (idx == 0)   { g_loss = 0.0; g_npairs = 0; }
}

// ---------------------------------------------------------------------------
// K1: per-row squared magnitude + int32 labels + label histogram
// ---------------------------------------------------------------------------
__global__ void __launch_bounds__(256) k_mag(const float* __restrict__ X,
                                             const int* __restrict__ T) {
    int warp = threadIdx.x >> 5;
    int lane = threadIdx.x & 31;
    int row  = blockIdx.x * 8 + warp;
    const float4* xr = (const float4*)(X + (size_t)row * D);
    float4 v = xr[lane];
    float s = v.x * v.x + v.y * v.y + v.z * v.z + v.w * v.w;
    #pragma unroll
    for (int off = 16; off; off >>= 1) s += __shfl_xor_sync(0xffffffff, s, off);
    if (lane == 0) {
        g_mag[row] = s;
        int t = T[row] & (NCLS - 1);
        g_t32[row] = t;
        atomicAdd(&g_hist[t], 1);
    }
}

// ---------------------------------------------------------------------------
// K2: symmetric tiled dist GEMM + fused epilogue
//   - masked exp(1-dist) row/col sums -> g_rowneg
//   - positive pairs (same label, gi<gj): (dist, i, j) compacted to smem
//     buffer, then one global atomic per block + coalesced flush.
// ---------------------------------------------------------------------------
__global__ void __launch_bounds__(256) k_dist(const float* __restrict__ X) {
    __shared__ float    As[32][128];
    __shared__ float    Bs[32][128];
    __shared__ float    rbuf[128];
    __shared__ float    cbuf[128];
    __shared__ float    ps_d[PB];
    __shared__ unsigned ps_ij[PB];
    __shared__ int      ps_n;
    __shared__ int      ps_base;

    int tid = threadIdx.x;
    if (tid == 0) ps_n = 0;

    int idx = blockIdx.x;
    int bi = 0, rem = idx;
    while (rem >= NT - bi) { rem -= NT - bi; bi++; }
    int bj = bi + rem;

    int tx = tid & 15, ty = tid >> 4;

    float acc[8][8];
    #pragma unroll
    for (int ii = 0; ii < 8; ii++)
        #pragma unroll
        for (int jj = 0; jj < 8; jj++) acc[ii][jj] = 0.f;

    const float4* Xv = (const float4*)X;

    for (int c = 0; c < 4; ++c) {          // K chunks of 32
        #pragma unroll
        for (int f = 0; f < 4; f++) {
            int e  = tid + 256 * f;        // 0..1023
            int r  = e & 127;
            int kc = e >> 7;               // float4 chunk within K-32 (0..7)
            float4 va = Xv[(size_t)(bi * 128 + r) * 32 + c * 8 + kc];
            float4 vb = Xv[(size_t)(bj * 128 + r) * 32 + c * 8 + kc];
            As[kc * 4 + 0][r] = va.x; As[kc * 4 + 1][r] = va.y;
            As[kc * 4 + 2][r] = va.z; As[kc * 4 + 3][r] = va.w;
            Bs[kc * 4 + 0][r] = vb.x; Bs[kc * 4 + 1][r] = vb.y;
            Bs[kc * 4 + 2][r] = vb.z; Bs[kc * 4 + 3][r] = vb.w;
        }
        __syncthreads();

        #pragma unroll 8
        for (int kk = 0; kk < 32; ++kk) {
            float4 a0 = *(const float4*)&As[kk][ty * 8];
            float4 a1 = *(const float4*)&As[kk][ty * 8 + 4];
            float4 b0 = *(const float4*)&Bs[kk][tx * 8];
            float4 b1 = *(const float4*)&Bs[kk][tx * 8 + 4];
            float a[8] = {a0.x, a0.y, a0.z, a0.w, a1.x, a1.y, a1.z, a1.w};
            float b[8] = {b0.x, b0.y, b0.z, b0.w, b1.x, b1.y, b1.z, b1.w};
            #pragma unroll
            for (int ii = 0; ii < 8; ii++)
                #pragma unroll
                for (int jj = 0; jj < 8; jj++)
                    acc[ii][jj] += a[ii] * b[jj];
        }
        __syncthreads();
    }

    // --- epilogue ---
    int i0 = bi * 128, j0 = bj * 128;
    float magi[8], magj[8];
    int   ti[8], tj[8];
    #pragma unroll
    for (int ii = 0; ii < 8; ii++) {
        int gi = i0 + ty * 8 + ii;
        magi[ii] = g_mag[gi]; ti[ii] = g_t32[gi];
    }
    #pragma unroll
    for (int jj = 0; jj < 8; jj++) {
        int gj = j0 + tx * 8 + jj;
        magj[jj] = g_mag[gj]; tj[jj] = g_t32[gj];
    }

    float rowsum[8] = {0, 0, 0, 0, 0, 0, 0, 0};
    float colsum[8] = {0, 0, 0, 0, 0, 0, 0, 0};

    #pragma unroll
    for (int ii = 0; ii < 8; ii++) {
        #pragma unroll
        for (int jj = 0; jj < 8; jj++) {
            float d2 = magi[ii] + magj[jj] - 2.f * acc[ii][jj];
            float dist = d2 > 0.f ? sqrtf(d2) : 0.f;
            if (ti[ii] != tj[jj]) {
                float e = __expf(1.0f - dist);
                rowsum[ii] += e;
                colsum[jj] += e;
            } else {
                int gi = i0 + ty * 8 + ii;
                int gj = j0 + tx * 8 + jj;
                if (gi < gj) {
                    int slot = atomicAdd(&ps_n, 1);
                    if (slot < PB) {
                        ps_d[slot]  = dist;
                        ps_ij[slot] = ((unsigned)gi << 12) | (unsigned)gj;
                    }
                }
            }
        }
    }

    #pragma unroll
    for (int ii = 0; ii < 8; ii++) {
        #pragma unroll
        for (int off = 1; off < 16; off <<= 1)
            rowsum[ii] += __shfl_xor_sync(0xffffffff, rowsum[ii], off);
    }
    #pragma unroll
    for (int jj = 0; jj < 8; jj++)
        colsum[jj] += __shfl_xor_sync(0xffffffff, colsum[jj], 16);

    if (tid < 128) { rbuf[tid] = 0.f; cbuf[tid] = 0.f; }
    __syncthreads();

    if (tx == 0) {
        #pragma unroll
        for (int ii = 0; ii < 8; ii++)
            atomicAdd(&rbuf[ty * 8 + ii], rowsum[ii]);
    }
    if ((ty & 1) == 0) {
        #pragma unroll
        for (int jj = 0; jj < 8; jj++)
            atomicAdd(&cbuf[tx * 8 + jj], colsum[jj]);
    }
    __syncthreads();

    if (tid < 128) {
        atomicAdd(&g_rowneg[i0 + tid], rbuf[tid]);
        if (bi != bj)
            atomicAdd(&g_rowneg[j0 + tid], cbuf[tid]);
    }

    // flush positive-pair buffer: one global atomic per block, coalesced copy
    if (tid == 0) {
        int n = ps_n < PB ? ps_n : PB;
        ps_base = atomicAdd(&g_npairs, n);
    }
    __syncthreads();
    int n = ps_n < PB ? ps_n : PB;
    int base = ps_base;
    for (int s = tid; s < n; s += 256) {
        g_pair_d[base + s]  = ps_d[s];
        g_pair_ij[base + s] = ps_ij[s];
    }
}

// ---------------------------------------------------------------------------
// K3: hinge^2 over compacted positive pairs (flat stride loop)
// ---------------------------------------------------------------------------
__global__ void __launch_bounds__(256) k_loss() {
    int np = g_npairs;
    float sum = 0.f;
    for (int p = blockIdx.x * 256 + threadIdx.x; p < np; p += gridDim.x * 256) {
        float dist  = g_pair_d[p];
        unsigned ij = g_pair_ij[p];
        int i = (int)(ij >> 12), j = (int)(ij & 4095u);
        float l = logf(g_rowneg[i] + g_rowneg[j]) + dist;
        if (l > 0.f) sum += l * l;
    }

    #pragma unroll
    for (int off = 16; off; off >>= 1) sum += __shfl_xor_sync(0xffffffff, sum, off);
    __shared__ float ws[8];
    if ((threadIdx.x & 31) == 0) ws[threadIdx.x >> 5] = sum;
    __syncthreads();
    if (threadIdx.x < 8) {
        float s = ws[threadIdx.x];
        #pragma unroll
        for (int off = 4; off; off >>= 1) s += __shfl_xor_sync(0xff, s, off);
        if (threadIdx.x == 0 && s != 0.f) atomicAdd(&g_loss, (double)s);
    }
}

// ---------------------------------------------------------------------------
// K4: counter = sum_c n_c*(n_c-1)/2 ; out = loss / (2*counter)
// ---------------------------------------------------------------------------
__global__ void k_final(float* __restrict__ out) {
    __shared__ long long cnt[NCLS];
    int t = threadIdx.x;
    long long n = (long long)g_hist[t];
    cnt[t] = n * (n - 1) / 2;
    __syncthreads();
    if (t == 0) {
        long long total = 0;
        #pragma unroll
        for (int c = 0; c < NCLS; c++) total += cnt[c];
        out[0] = (float)(g_loss / (2.0 * (double)total));
    }
}

// ---------------------------------------------------------------------------
extern "C" void kernel_launch(void* const* d_in, const int* in_sizes, int n_in,
                              void* d_out, int out_size) {
    const float* X   = (const float*)d_in[0];
    const int*   T   = (const int*)d_in[1];      // int32: JAX x64 disabled
    float*       out = (float*)d_out;

    k_init<<<16, 256>>>();
    k_mag<<<B / 8, 256>>>(X, T);
    k_dist<<<NT * (NT + 1) / 2, 256>>>(X);
    k_loss<<<256, 256>>>();
    k_final<<<1, NCLS>>>(out);
}

// round 6
// speedup vs baseline: 3.7052x; 1.1416x over previous
#include <cuda_runtime.h>
#include <cuda_bf16.h>
#include <math.h>
#include <stdint.h>

#define B 4096
#define D 128
#define NT 32              // 4096 / 128 tiles per dimension
#define NCLS 64
#define PB 2048            // per-block positive-pair buffer (expected ~256)
#define PAIR_CAP (1 << 20)

// ---- scratch (device globals; no allocation allowed) ----
__device__ float    g_rowneg[B];
__device__ float    g_mag[B];
__device__ int      g_t32[B];
__device__ int      g_hist[NCLS];
__device__ int      g_npairs;
__device__ float    g_pair_d[PAIR_CAP];
__device__ unsigned g_pair_ij[PAIR_CAP];
__device__ double   g_loss;

static __device__ __forceinline__ uint32_t smem_u32(const void* p) {
    uint32_t a;
    asm("{ .reg .u64 t; cvta.to.shared.u64 t, %1; cvt.u32.u64 %0, t; }"
        : "=r"(a) : "l"(p));
    return a;
}

// ---- dynamic smem layout (bytes); bf16 tiles padded to 136 elems/row ----
#define LDT 272            // 136 * 2 bytes, row stride of bf16 tiles
#define OFF_A_HI 0
#define OFF_A_LO 34816
#define OFF_B_HI 69632
#define OFF_B_LO 104448
#define OFF_E    0         // fp32 [128][132] overlays A_HI+A_LO after MMA
#define OFF_PSD  139264
#define OFF_PSIJ 147456
#define OFF_MAGI 155648
#define OFF_MAGJ 156160
#define OFF_TI   156672
#define OFF_TJ   157184
#define OFF_PSN  157696
#define OFF_PSBASE 157700
#define SMEM_TOTAL 157760

#define LDSM4(r0, r1, r2, r3, a)                                         \
    asm volatile("ldmatrix.sync.aligned.m8n8.x4.shared.b16 "             \
                 "{%0,%1,%2,%3}, [%4];"                                  \
                 : "=r"(r0), "=r"(r1), "=r"(r2), "=r"(r3) : "r"(a))

#define MMA_BF16(c, a0, a1, a2, a3, b0, b1)                              \
    asm volatile("mma.sync.aligned.m16n8k16.row.col.f32.bf16.bf16.f32 "  \
                 "{%0,%1,%2,%3}, {%4,%5,%6,%7}, {%8,%9}, {%0,%1,%2,%3};" \
                 : "+f"((c)[0]), "+f"((c)[1]), "+f"((c)[2]), "+f"((c)[3])\
                 : "r"(a0), "r"(a1), "r"(a2), "r"(a3), "r"(b0), "r"(b1))

// pack two floats -> bf16x2 (lo elem in low half)
static __device__ __forceinline__ uint32_t pack_bf2(float lo, float hi) {
    uint32_t r;
    asm("cvt.rn.bf16x2.f32 %0, %1, %2;" : "=r"(r) : "f"(hi), "f"(lo));
    return r;
}
static __device__ __forceinline__ float bf_hi_part(float x) {
    __nv_bfloat16 h = __float2bfloat16_rn(x);
    return __bfloat162float(h);
}

// ---------------------------------------------------------------------------
__global__ void k_init() {
    int idx = blockIdx.x * blockDim.x + threadIdx.x;
    if (idx < B)    g_rowneg[idx] = 0.f;
    if (idx < NCLS) g_hist[idx] = 0;
    if (idx == 0)   { g_loss = 0.0; g_npairs = 0; }
}

// K1: magnitudes (fp32-exact), labels, histogram
__global__ void __launch_bounds__(256) k_mag(const float* __restrict__ X,
                                             const int* __restrict__ T) {
    int warp = threadIdx.x >> 5, lane = threadIdx.x & 31;
    int row  = blockIdx.x * 8 + warp;
    const float4* xr = (const float4*)(X + (size_t)row * D);
    float4 v = xr[lane];
    float s = v.x * v.x + v.y * v.y + v.z * v.z + v.w * v.w;
    #pragma unroll
    for (int off = 16; off; off >>= 1) s += __shfl_xor_sync(0xffffffff, s, off);
    if (lane == 0) {
        g_mag[row] = s;
        int t = T[row] & (NCLS - 1);
        g_t32[row] = t;
        atomicAdd(&g_hist[t], 1);
    }
}

// ---------------------------------------------------------------------------
// K2: Gram tile via mma.sync bf16 (3-product split) + fused epilogue
// ---------------------------------------------------------------------------
__global__ void __launch_bounds__(256) k_dist(const float* __restrict__ X) {
    extern __shared__ char smem[];
    uint32_t sb = smem_u32(smem);
    int tid = threadIdx.x;

    if (tid == 0) *(int*)(smem + OFF_PSN) = 0;

    // triangular block decode -> (bi, bj), bi <= bj
    int idx = blockIdx.x, bi = 0, rem = idx;
    while (rem >= NT - bi) { rem -= NT - bi; bi++; }
    int bj = bi + rem;
    int i0 = bi * 128, j0 = bj * 128;

    // --- load tiles, split fp32 -> hi/lo bf16, store padded smem ---
    const float4* Xv = (const float4*)X;
    #pragma unroll
    for (int side = 0; side < 2; side++) {
        int row0 = side ? j0 : i0;
        char* hiB = smem + (side ? OFF_B_HI : OFF_A_HI);
        char* loB = smem + (side ? OFF_B_LO : OFF_A_LO);
        #pragma unroll
        for (int it = 0; it < 16; it++) {
            int e = it * 256 + tid;          // 0..4095 float4 slots
            int r = e >> 5, kc = e & 31;
            float4 v = Xv[(size_t)(row0 + r) * 32 + kc];
            float hx = bf_hi_part(v.x), hy = bf_hi_part(v.y);
            float hz = bf_hi_part(v.z), hw = bf_hi_part(v.w);
            uint2 hp = { pack_bf2(hx, hy), pack_bf2(hz, hw) };
            uint2 lp = { pack_bf2(v.x - hx, v.y - hy),
                         pack_bf2(v.z - hz, v.w - hw) };
            *(uint2*)(hiB + r * LDT + kc * 8) = hp;
            *(uint2*)(loB + r * LDT + kc * 8) = lp;
        }
    }
    if (tid < 128) {
        ((float*)(smem + OFF_MAGI))[tid] = g_mag[i0 + tid];
        ((float*)(smem + OFF_MAGJ))[tid] = g_mag[j0 + tid];
        ((int*)(smem + OFF_TI))[tid]     = g_t32[i0 + tid];
        ((int*)(smem + OFF_TJ))[tid]     = g_t32[j0 + tid];
    }
    __syncthreads();

    // --- MMA: warp grid 2(m) x 4(n); each warp 64x32 ---
    int wid = tid >> 5, lane = tid & 31;
    int wm = wid & 1, wn = wid >> 1;

    float acc[4][4][4];
    #pragma unroll
    for (int mt = 0; mt < 4; mt++)
        #pragma unroll
        for (int nt = 0; nt < 4; nt++)
            #pragma unroll
            for (int q = 0; q < 4; q++) acc[mt][nt][q] = 0.f;

    uint32_t aRowOff = ((lane & 7) + ((lane >> 3) & 1) * 8) * LDT + (lane >> 4) * 16;
    uint32_t bRowOff = ((lane & 7) + (lane >> 4) * 8) * LDT + ((lane >> 3) & 1) * 16;
    uint32_t aHiBase = sb + OFF_A_HI + wm * 64 * LDT + aRowOff;
    uint32_t aLoBase = sb + OFF_A_LO + wm * 64 * LDT + aRowOff;
    uint32_t bHiBase = sb + OFF_B_HI + wn * 32 * LDT + bRowOff;
    uint32_t bLoBase = sb + OFF_B_LO + wn * 32 * LDT + bRowOff;

    for (int ks = 0; ks < 8; ks++) {
        uint32_t ko = ks * 32;
        uint32_t bh[8], bl[8];
        LDSM4(bh[0], bh[1], bh[2], bh[3], bHiBase + ko);
        LDSM4(bh[4], bh[5], bh[6], bh[7], bHiBase + 16 * LDT + ko);
        LDSM4(bl[0], bl[1], bl[2], bl[3], bLoBase + ko);
        LDSM4(bl[4], bl[5], bl[6], bl[7], bLoBase + 16 * LDT + ko);
        #pragma unroll
        for (int mt = 0; mt < 4; mt++) {
            uint32_t ah[4], al[4];
            LDSM4(ah[0], ah[1], ah[2], ah[3], aHiBase + mt * 16 * LDT + ko);
            LDSM4(al[0], al[1], al[2], al[3], aLoBase + mt * 16 * LDT + ko);
            #pragma unroll
            for (int nt = 0; nt < 4; nt++) {
                MMA_BF16(acc[mt][nt], ah[0], ah[1], ah[2], ah[3],
                         bh[nt * 2], bh[nt * 2 + 1]);
                MMA_BF16(acc[mt][nt], ah[0], ah[1], ah[2], ah[3],
                         bl[nt * 2], bl[nt * 2 + 1]);
                MMA_BF16(acc[mt][nt], al[0], al[1], al[2], al[3],
                         bh[nt * 2], bh[nt * 2 + 1]);
            }
        }
    }
    __syncthreads();                 // tiles dead; overlay E

    // --- write sim accumulators to E[128][132] fp32 ---
    float* E = (float*)(smem + OFF_E);
    int qr = lane >> 2, qc = (lane & 3) * 2;
    #pragma unroll
    for (int mt = 0; mt < 4; mt++)
        #pragma unroll
        for (int nt = 0; nt < 4; nt++) {
            int row = wm * 64 + mt * 16 + qr;
            int col = wn * 32 + nt * 8 + qc;
            *(float2*)&E[row * 132 + col]       = make_float2(acc[mt][nt][0], acc[mt][nt][1]);
            *(float2*)&E[(row + 8) * 132 + col] = make_float2(acc[mt][nt][2], acc[mt][nt][3]);
        }
    __syncthreads();

    // --- epilogue: 256 threads, 2 per row (64 cols each) ---
    const float* magjs = (const float*)(smem + OFF_MAGJ);
    const int*   tjs   = (const int*)(smem + OFF_TJ);
    float* psd = (float*)(smem + OFF_PSD);
    unsigned* psij = (unsigned*)(smem + OFF_PSIJ);
    int* psn = (int*)(smem + OFF_PSN);

    {
        int row  = tid & 127;
        int cb   = (tid >> 7) * 64;
        float mi  = ((const float*)(smem + OFF_MAGI))[row];
        int   til = ((const int*)(smem + OFF_TI))[row];
        float rowsum = 0.f;
        #pragma unroll 4
        for (int c = 0; c < 64; c++) {
            int col = cb + c;
            float sim = E[row * 132 + col];
            float d2 = mi + magjs[col] - 2.f * sim;
            float dist = d2 > 0.f ? sqrtf(d2) : 0.f;
            float e = 0.f;
            if (til != tjs[col]) {
                e = __expf(1.0f - dist);
                rowsum += e;
            } else {
                int gi = i0 + row, gj = j0 + col;
                if (gi < gj) {
                    int slot = atomicAdd(psn, 1);
                    if (slot < PB) {
                        psd[slot]  = dist;
                        psij[slot] = ((unsigned)gi << 12) | (unsigned)gj;
                    }
                }
            }
            E[row * 132 + col] = e;
        }
        atomicAdd(&g_rowneg[i0 + row], rowsum);
    }
    __syncthreads();

    if (bi != bj && tid < 128) {     // column sums via symmetry
        float cs = 0.f;
        #pragma unroll 4
        for (int i = 0; i < 128; i++) cs += E[i * 132 + tid];
        atomicAdd(&g_rowneg[j0 + tid], cs);
    }

    // flush positive pairs: one global atomic + coalesced copy
    if (tid == 0) {
        int n = *psn; if (n > PB) n = PB;
        *(int*)(smem + OFF_PSBASE) = atomicAdd(&g_npairs, n);
    }
    __syncthreads();
    int n = *psn; if (n > PB) n = PB;
    int base = *(int*)(smem + OFF_PSBASE);
    for (int s = tid; s < n; s += 256) {
        g_pair_d[base + s]  = psd[s];
        g_pair_ij[base + s] = psij[s];
    }
}

// ---------------------------------------------------------------------------
// K3: hinge^2 over compacted positive pairs
// ---------------------------------------------------------------------------
__global__ void __launch_bounds__(256) k_loss() {
    int np = g_npairs;
    float sum = 0.f;
    for (int p = blockIdx.x * 256 + threadIdx.x; p < np; p += gridDim.x * 256) {
        float dist  = g_pair_d[p];
        unsigned ij = g_pair_ij[p];
        int i = (int)(ij >> 12), j = (int)(ij & 4095u);
        float l = logf(g_rowneg[i] + g_rowneg[j]) + dist;
        if (l > 0.f) sum += l * l;
    }
    #pragma unroll
    for (int off = 16; off; off >>= 1) sum += __shfl_xor_sync(0xffffffff, sum, off);
    __shared__ float ws[8];
    if ((threadIdx.x & 31) == 0) ws[threadIdx.x >> 5] = sum;
    __syncthreads();
    if (threadIdx.x < 8) {
        float s = ws[threadIdx.x];
        #pragma unroll
        for (int off = 4; off; off >>= 1) s += __shfl_xor_sync(0xff, s, off);
        if (threadIdx.x == 0 && s != 0.f) atomicAdd(&g_loss, (double)s);
    }
}

// ---------------------------------------------------------------------------
__global__ void k_final(float* __restrict__ out) {
    __shared__ long long cnt[NCLS];
    int t = threadIdx.x;
    long long n = (long long)g_hist[t];
    cnt[t] = n * (n - 1) / 2;
    __syncthreads();
    if (t == 0) {
        long long total = 0;
        #pragma unroll
        for (int c = 0; c < NCLS; c++) total += cnt[c];
        out[0] = (float)(g_loss / (2.0 * (double)total));
    }
}

// ---------------------------------------------------------------------------
extern "C" void kernel_launch(void* const* d_in, const int* in_sizes, int n_in,
                              void* d_out, int out_size) {
    const float* X   = (const float*)d_in[0];
    const int*   T   = (const int*)d_in[1];
    float*       out = (float*)d_out;

    cudaFuncSetAttribute(k_dist, cudaFuncAttributeMaxDynamicSharedMemorySize,
                         SMEM_TOTAL);

    k_init<<<16, 256>>>();
    k_mag<<<B / 8, 256>>>(X, T);
    k_dist<<<NT * (NT + 1) / 2, 256, SMEM_TOTAL>>>(X);
    k_loss<<<256, 256>>>();
    k_final<<<1, NCLS>>>(out);
}

// round 7
// speedup vs baseline: 5.6726x; 1.5310x over previous
#include <cuda_runtime.h>
#include <cuda_bf16.h>
#include <math.h>
#include <stdint.h>

#define B 4096
#define D 128
#define NT 32              // 4096 / 128 tiles per dimension
#define NCLS 64
#define PB 1024            // per-block positive-pair buffer (expected ~256)
#define PAIR_CAP (1 << 20)

// ---- scratch (device globals; no allocation allowed) ----
__device__ float         g_rowneg[B];
__device__ float         g_mag[B];
__device__ int           g_t32[B];
__device__ int           g_hist[NCLS];
__device__ int           g_npairs;
__device__ float         g_pair_d[PAIR_CAP];
__device__ unsigned      g_pair_ij[PAIR_CAP];
__device__ double        g_loss;
__device__ __nv_bfloat16 g_hi[(size_t)B * D];
__device__ __nv_bfloat16 g_lo[(size_t)B * D];

static __device__ __forceinline__ uint32_t smem_u32(const void* p) {
    uint32_t a;
    asm("{ .reg .u64 t; cvta.to.shared.u64 t, %1; cvt.u32.u64 %0, t; }"
        : "=r"(a) : "l"(p));
    return a;
}

// ---- smem layout (bytes); bf16 K-chunk tiles 128 x 64, padded to 72 cols ----
#define LDT 144            // 72 * 2 bytes
#define TILE_BYTES 18432   // 128 * 144
#define OFF_AHI 0
#define OFF_ALO 18432
#define OFF_BHI 36864
#define OFF_BLO 55296
#define OFF_PSD 73728
#define OFF_PSIJ 77824
#define OFF_MAGI 81920
#define OFF_MAGJ 82432
#define OFF_TI 82944
#define OFF_TJ 83456
#define OFF_RBUF 83968
#define OFF_CBUF 84480
#define OFF_PSN 84992
#define OFF_PSBASE 84996
#define SMEM_TOTAL 85504

#define LDSM4(r0, r1, r2, r3, a)                                         \
    asm volatile("ldmatrix.sync.aligned.m8n8.x4.shared.b16 "             \
                 "{%0,%1,%2,%3}, [%4];"                                  \
                 : "=r"(r0), "=r"(r1), "=r"(r2), "=r"(r3) : "r"(a))

#define MMA_BF16(c, a0, a1, a2, a3, b0, b1)                              \
    asm volatile("mma.sync.aligned.m16n8k16.row.col.f32.bf16.bf16.f32 "  \
                 "{%0,%1,%2,%3}, {%4,%5,%6,%7}, {%8,%9}, {%0,%1,%2,%3};" \
                 : "+f"((c)[0]), "+f"((c)[1]), "+f"((c)[2]), "+f"((c)[3])\
                 : "r"(a0), "r"(a1), "r"(a2), "r"(a3), "r"(b0), "r"(b1))

static __device__ __forceinline__ uint32_t pack_bf2(float lo, float hi) {
    uint32_t r;
    asm("cvt.rn.bf16x2.f32 %0, %1, %2;" : "=r"(r) : "f"(hi), "f"(lo));
    return r;
}
static __device__ __forceinline__ float bf_hi_part(float x) {
    return __bfloat162float(__float2bfloat16_rn(x));
}

// ---------------------------------------------------------------------------
__global__ void k_init() {
    int idx = blockIdx.x * blockDim.x + threadIdx.x;
    if (idx < B)    g_rowneg[idx] = 0.f;
    if (idx < NCLS) g_hist[idx] = 0;
    if (idx == 0)   { g_loss = 0.0; g_npairs = 0; }
}

// K1: magnitudes (fp32-exact), labels, histogram
__global__ void __launch_bounds__(256) k_mag(const float* __restrict__ X,
                                             const int* __restrict__ T) {
    int warp = threadIdx.x >> 5, lane = threadIdx.x & 31;
    int row  = blockIdx.x * 8 + warp;
    const float4* xr = (const float4*)(X + (size_t)row * D);
    float4 v = xr[lane];
    float s = v.x * v.x + v.y * v.y + v.z * v.z + v.w * v.w;
    #pragma unroll
    for (int off = 16; off; off >>= 1) s += __shfl_xor_sync(0xffffffff, s, off);
    if (lane == 0) {
        g_mag[row] = s;
        int t = T[row] & (NCLS - 1);
        g_t32[row] = t;
        atomicAdd(&g_hist[t], 1);
    }
}

// K1b: X -> hi (bf16) + lo (bf16 residual), done once
__global__ void __launch_bounds__(256) k_split(const float* __restrict__ X) {
    int i = blockIdx.x * 256 + threadIdx.x;        // 4 floats each
    float4 v = ((const float4*)X)[i];
    float hx = bf_hi_part(v.x), hy = bf_hi_part(v.y);
    float hz = bf_hi_part(v.z), hw = bf_hi_part(v.w);
    uint2 hp = { pack_bf2(hx, hy), pack_bf2(hz, hw) };
    uint2 lp = { pack_bf2(v.x - hx, v.y - hy), pack_bf2(v.z - hz, v.w - hw) };
    ((uint2*)g_hi)[i] = hp;
    ((uint2*)g_lo)[i] = lp;
}

// ---------------------------------------------------------------------------
// K2: Gram tile via mma.sync bf16 (3-product split), K-chunked, 2 CTAs/SM,
//     register epilogue (no E matrix round-trip).
// ---------------------------------------------------------------------------
__global__ void __launch_bounds__(256, 2) k_dist() {
    extern __shared__ char smem[];
    uint32_t sb = smem_u32(smem);
    int tid = threadIdx.x;

    if (tid == 0) *(int*)(smem + OFF_PSN) = 0;

    // triangular block decode -> (bi, bj), bi <= bj
    int idx = blockIdx.x, bi = 0, rem = idx;
    while (rem >= NT - bi) { rem -= NT - bi; bi++; }
    int bj = bi + rem;
    int i0 = bi * 128, j0 = bj * 128;

    float* magis = (float*)(smem + OFF_MAGI);
    float* magjs = (float*)(smem + OFF_MAGJ);
    int*   tis   = (int*)(smem + OFF_TI);
    int*   tjs   = (int*)(smem + OFF_TJ);
    float* rbuf  = (float*)(smem + OFF_RBUF);
    float* cbuf  = (float*)(smem + OFF_CBUF);

    if (tid < 128) {
        magis[tid] = g_mag[i0 + tid];
        magjs[tid] = g_mag[j0 + tid];
        tis[tid]   = g_t32[i0 + tid];
        tjs[tid]   = g_t32[j0 + tid];
        rbuf[tid] = 0.f; cbuf[tid] = 0.f;
    }

    int wid = tid >> 5, lane = tid & 31;
    int wm = wid & 1, wn = wid >> 1;

    float acc[4][4][4];
    #pragma unroll
    for (int mt = 0; mt < 4; mt++)
        #pragma unroll
        for (int nt = 0; nt < 4; nt++)
            #pragma unroll
            for (int q = 0; q < 4; q++) acc[mt][nt][q] = 0.f;

    uint32_t aRowOff = ((lane & 7) + ((lane >> 3) & 1) * 8) * LDT + (lane >> 4) * 16;
    uint32_t bRowOff = ((lane & 7) + (lane >> 4) * 8) * LDT + ((lane >> 3) & 1) * 16;
    uint32_t aHiBase = sb + OFF_AHI + wm * 64 * LDT + aRowOff;
    uint32_t aLoBase = sb + OFF_ALO + wm * 64 * LDT + aRowOff;
    uint32_t bHiBase = sb + OFF_BHI + wn * 32 * LDT + bRowOff;
    uint32_t bLoBase = sb + OFF_BLO + wn * 32 * LDT + bRowOff;

    #pragma unroll
    for (int chunk = 0; chunk < 2; chunk++) {
        if (chunk) __syncthreads();        // prior LDSM reads complete

        // load 4 tiles (A_hi, A_lo, B_hi, B_lo) for this K-half
        #pragma unroll
        for (int it = 0; it < 16; it++) {
            int e = it * 256 + tid;        // 0..4095 16B-chunks
            int tile = e >> 10;
            int w = e & 1023;
            int r = w >> 3, kc = w & 7;
            const __nv_bfloat16* src = (tile & 1) ? g_lo : g_hi;
            int row0 = (tile >> 1) ? j0 : i0;
            uint4 v = *(const uint4*)(src + (size_t)(row0 + r) * D + chunk * 64 + kc * 8);
            *(uint4*)(smem + tile * TILE_BYTES + r * LDT + kc * 16) = v;
        }
        __syncthreads();

        #pragma unroll
        for (int ks = 0; ks < 4; ks++) {
            uint32_t ko = ks * 32;
            uint32_t bh[8], bl[8];
            LDSM4(bh[0], bh[1], bh[2], bh[3], bHiBase + ko);
            LDSM4(bh[4], bh[5], bh[6], bh[7], bHiBase + 16 * LDT + ko);
            LDSM4(bl[0], bl[1], bl[2], bl[3], bLoBase + ko);
            LDSM4(bl[4], bl[5], bl[6], bl[7], bLoBase + 16 * LDT + ko);
            #pragma unroll
            for (int mt = 0; mt < 4; mt++) {
                uint32_t ah[4], al[4];
                LDSM4(ah[0], ah[1], ah[2], ah[3], aHiBase + mt * 16 * LDT + ko);
                LDSM4(al[0], al[1], al[2], al[3], aLoBase + mt * 16 * LDT + ko);
                #pragma unroll
                for (int nt = 0; nt < 4; nt++) {
                    MMA_BF16(acc[mt][nt], ah[0], ah[1], ah[2], ah[3],
                             bh[nt * 2], bh[nt * 2 + 1]);
                    MMA_BF16(acc[mt][nt], ah[0], ah[1], ah[2], ah[3],
                             bl[nt * 2], bl[nt * 2 + 1]);
                    MMA_BF16(acc[mt][nt], al[0], al[1], al[2], al[3],
                             bh[nt * 2], bh[nt * 2 + 1]);
                }
            }
        }
    }

    // --- register epilogue ---
    int qr = lane >> 2, qc2 = (lane & 3) * 2;
    float* psd = (float*)(smem + OFF_PSD);
    unsigned* psij = (unsigned*)(smem + OFF_PSIJ);
    int* psn = (int*)(smem + OFF_PSN);

    float magi_r[8]; int ti_r[8];
    #pragma unroll
    for (int mt = 0; mt < 4; mt++)
        #pragma unroll
        for (int h = 0; h < 2; h++) {
            int rl = wm * 64 + mt * 16 + qr + h * 8;
            magi_r[mt * 2 + h] = magis[rl];
            ti_r[mt * 2 + h]   = tis[rl];
        }

    float rowsum[8] = {0,0,0,0,0,0,0,0};
    float colsum[8] = {0,0,0,0,0,0,0,0};

    #pragma unroll
    for (int nt = 0; nt < 4; nt++) {
        int cl = wn * 32 + nt * 8 + qc2;
        float mj0 = magjs[cl], mj1 = magjs[cl + 1];
        int   tj0 = tjs[cl],   tj1 = tjs[cl + 1];
        #pragma unroll
        for (int mt = 0; mt < 4; mt++) {
            #pragma unroll
            for (int h = 0; h < 2; h++) {
                int ri = mt * 2 + h;
                int rl = wm * 64 + mt * 16 + qr + h * 8;
                #pragma unroll
                for (int v = 0; v < 2; v++) {
                    float sim = acc[mt][nt][h * 2 + v];
                    float mj  = v ? mj1 : mj0;
                    int   tj  = v ? tj1 : tj0;
                    float d2 = magi_r[ri] + mj - 2.f * sim;
                    float dist = d2 > 0.f ? sqrtf(d2) : 0.f;
                    if (ti_r[ri] != tj) {
                        float e = __expf(1.0f - dist);
                        rowsum[ri] += e;
                        colsum[nt * 2 + v] += e;
                    } else {
                        int gi = i0 + rl, gj = j0 + cl + v;
                        if (gi < gj) {
                            int slot = atomicAdd(psn, 1);
                            if (slot < PB) {
                                psd[slot]  = dist;
                                psij[slot] = ((unsigned)gi << 12) | (unsigned)gj;
                            }
                        }
                    }
                }
            }
        }
    }

    // rowsum: reduce across the 4 lanes of each quad (same qr)
    #pragma unroll
    for (int k = 0; k < 8; k++) {
        rowsum[k] += __shfl_xor_sync(0xffffffff, rowsum[k], 1);
        rowsum[k] += __shfl_xor_sync(0xffffffff, rowsum[k], 2);
        colsum[k] += __shfl_xor_sync(0xffffffff, colsum[k], 4);
        colsum[k] += __shfl_xor_sync(0xffffffff, colsum[k], 8);
        colsum[k] += __shfl_xor_sync(0xffffffff, colsum[k], 16);
    }
    if ((lane & 3) == 0) {
        #pragma unroll
        for (int mt = 0; mt < 4; mt++)
            #pragma unroll
            for (int h = 0; h < 2; h++)
                atomicAdd(&rbuf[wm * 64 + mt * 16 + qr + h * 8],
                          rowsum[mt * 2 + h]);
    }
    if (lane < 4) {
        #pragma unroll
        for (int nt = 0; nt < 4; nt++)
            #pragma unroll
            for (int v = 0; v < 2; v++)
                atomicAdd(&cbuf[wn * 32 + nt * 8 + lane * 2 + v],
                          colsum[nt * 2 + v]);
    }
    __syncthreads();

    if (tid < 128) {
        atomicAdd(&g_rowneg[i0 + tid], rbuf[tid]);
        if (bi != bj) atomicAdd(&g_rowneg[j0 + tid], cbuf[tid]);
    }

    // flush positive pairs: one global atomic + coalesced copy
    if (tid == 0) {
        int n = *psn; if (n > PB) n = PB;
        *(int*)(smem + OFF_PSBASE) = atomicAdd(&g_npairs, n);
    }
    __syncthreads();
    int n = *psn; if (n > PB) n = PB;
    int base = *(int*)(smem + OFF_PSBASE);
    for (int s = tid; s < n; s += 256) {
        g_pair_d[base + s]  = psd[s];
        g_pair_ij[base + s] = psij[s];
    }
}

// ---------------------------------------------------------------------------
// K3: hinge^2 over compacted positive pairs
// ---------------------------------------------------------------------------
__global__ void __launch_bounds__(256) k_loss() {
    int np = g_npairs;
    float sum = 0.f;
    for (int p = blockIdx.x * 256 + threadIdx.x; p < np; p += gridDim.x * 256) {
        float dist  = g_pair_d[p];
        unsigned ij = g_pair_ij[p];
        int i = (int)(ij >> 12), j = (int)(ij & 4095u);
        float l = logf(g_rowneg[i] + g_rowneg[j]) + dist;
        if (l > 0.f) sum += l * l;
    }
    #pragma unroll
    for (int off = 16; off; off >>= 1) sum += __shfl_xor_sync(0xffffffff, sum, off);
    __shared__ float ws[8];
    if ((threadIdx.x & 31) == 0) ws[threadIdx.x >> 5] = sum;
    __syncthreads();
    if (threadIdx.x < 8) {
        float s = ws[threadIdx.x];
        #pragma unroll
        for (int off = 4; off; off >>= 1) s += __shfl_xor_sync(0xff, s, off);
        if (threadIdx.x == 0 && s != 0.f) atomicAdd(&g_loss, (double)s);
    }
}

// ---------------------------------------------------------------------------
__global__ void k_final(float* __restrict__ out) {
    __shared__ long long cnt[NCLS];
    int t = threadIdx.x;
    long long n = (long long)g_hist[t];
    cnt[t] = n * (n - 1) / 2;
    __syncthreads();
    if (t == 0) {
        long long total = 0;
        #pragma unroll
        for (int c = 0; c < NCLS; c++) total += cnt[c];
        out[0] = (float)(g_loss / (2.0 * (double)total));
    }
}

// ---------------------------------------------------------------------------
extern "C" void kernel_launch(void* const* d_in, const int* in_sizes, int n_in,
                              void* d_out, int out_size) {
    const float* X   = (const float*)d_in[0];
    const int*   T   = (const int*)d_in[1];
    float*       out = (float*)d_out;

    cudaFuncSetAttribute(k_dist, cudaFuncAttributeMaxDynamicSharedMemorySize,
                         SMEM_TOTAL);

    k_init<<<16, 256>>>();
    k_mag<<<B / 8, 256>>>(X, T);
    k_split<<<(B * D / 4) / 256, 256>>>(X);
    k_dist<<<NT * (NT + 1) / 2, 256, SMEM_TOTAL>>>();
    k_loss<<<256, 256>>>();
    k_final<<<1, NCLS>>>(out);
}

// round 8
// speedup vs baseline: 6.1084x; 1.0768x over previous
#include <cuda_runtime.h>
#include <cuda_bf16.h>
#include <math.h>
#include <stdint.h>

#define B 4096
#define D 128
#define NT 32              // 4096 / 128 tiles per dimension
#define NCLS 64
#define PB 1024            // per-block positive-pair buffer (expected ~256)
#define PAIR_CAP (1 << 20)

// ---- scratch (device globals; no allocation allowed) ----
__device__ float    g_rowneg[B];
__device__ float    g_mag[B];
__device__ int      g_t32[B];
__device__ int      g_hist[NCLS];
__device__ int      g_npairs;
__device__ float    g_pair_d[PAIR_CAP];
__device__ unsigned g_pair_ij[PAIR_CAP];
__device__ double   g_loss;
__device__ __align__(256) __nv_bfloat16 g_hi[(size_t)B * D];
__device__ __align__(256) __nv_bfloat16 g_lo[(size_t)B * D];

static __device__ __forceinline__ uint32_t smem_u32(const void* p) {
    uint32_t a;
    asm("{ .reg .u64 t; cvta.to.shared.u64 t, %1; cvt.u32.u64 %0, t; }"
        : "=r"(a) : "l"(p));
    return a;
}

// ---- smem layout: 2 buffers x 4 tiles x [128 rows x 80 B] (K=32 chunks) ----
#define LDT 80
#define TILE_B 10240       // 128 * 80
#define BUF_B 40960        // 4 tiles
#define OFF_TILES 0        // 81920
#define OFF_MAGI 81920
#define OFF_MAGJ 82432
#define OFF_TI   82944
#define OFF_TJ   83456
#define OFF_RBUF 83968
#define OFF_CBUF 84480
#define OFF_PSD  84992     // 4096
#define OFF_PSIJ 89088     // 4096
#define OFF_PSN  93184
#define OFF_PSBASE 93188
#define SMEM_TOTAL 93248

#define LDSM4(r0, r1, r2, r3, a)                                         \
    asm volatile("ldmatrix.sync.aligned.m8n8.x4.shared.b16 "             \
                 "{%0,%1,%2,%3}, [%4];"                                  \
                 : "=r"(r0), "=r"(r1), "=r"(r2), "=r"(r3) : "r"(a))

#define MMA_BF16(c, a0, a1, a2, a3, b0, b1)                              \
    asm volatile("mma.sync.aligned.m16n8k16.row.col.f32.bf16.bf16.f32 "  \
                 "{%0,%1,%2,%3}, {%4,%5,%6,%7}, {%8,%9}, {%0,%1,%2,%3};" \
                 : "+f"((c)[0]), "+f"((c)[1]), "+f"((c)[2]), "+f"((c)[3])\
                 : "r"(a0), "r"(a1), "r"(a2), "r"(a3), "r"(b0), "r"(b1))

#define CP_ASYNC16(s, g)                                                 \
    asm volatile("cp.async.cg.shared.global [%0], [%1], 16;"             \
                 :: "r"(s), "l"(g))
#define CP_COMMIT() asm volatile("cp.async.commit_group;" ::: "memory")
#define CP_WAIT(n)  asm volatile("cp.async.wait_group %0;" :: "n"(n) : "memory")

static __device__ __forceinline__ uint32_t pack_bf2(float lo, float hi) {
    uint32_t r;
    asm("cvt.rn.bf16x2.f32 %0, %1, %2;" : "=r"(r) : "f"(hi), "f"(lo));
    return r;
}
static __device__ __forceinline__ float bf_hi_part(float x) {
    return __bfloat162float(__float2bfloat16_rn(x));
}
static __device__ __forceinline__ float sqrt_approx(float x) {
    float r;
    asm("sqrt.approx.f32 %0, %1;" : "=f"(r) : "f"(x));
    return r;
}

// ---------------------------------------------------------------------------
__global__ void k_init() {
    int idx = blockIdx.x * blockDim.x + threadIdx.x;
    if (idx < B)    g_rowneg[idx] = 0.f;
    if (idx < NCLS) g_hist[idx] = 0;
    if (idx == 0)   { g_loss = 0.0; g_npairs = 0; }
}

// K1: magnitudes (fp32-exact), labels, histogram
__global__ void __launch_bounds__(256) k_mag(const float* __restrict__ X,
                                             const int* __restrict__ T) {
    int warp = threadIdx.x >> 5, lane = threadIdx.x & 31;
    int row  = blockIdx.x * 8 + warp;
    const float4* xr = (const float4*)(X + (size_t)row * D);
    float4 v = xr[lane];
    float s = v.x * v.x + v.y * v.y + v.z * v.z + v.w * v.w;
    #pragma unroll
    for (int off = 16; off; off >>= 1) s += __shfl_xor_sync(0xffffffff, s, off);
    if (lane == 0) {
        g_mag[row] = s;
        int t = T[row] & (NCLS - 1);
        g_t32[row] = t;
        atomicAdd(&g_hist[t], 1);
    }
}

// K1b: X -> hi (bf16) + lo (bf16 residual), done once
__global__ void __launch_bounds__(256) k_split(const float* __restrict__ X) {
    int i = blockIdx.x * 256 + threadIdx.x;        // 4 floats each
    float4 v = ((const float4*)X)[i];
    float hx = bf_hi_part(v.x), hy = bf_hi_part(v.y);
    float hz = bf_hi_part(v.z), hw = bf_hi_part(v.w);
    uint2 hp = { pack_bf2(hx, hy), pack_bf2(hz, hw) };
    uint2 lp = { pack_bf2(v.x - hx, v.y - hy), pack_bf2(v.z - hz, v.w - hw) };
    ((uint2*)g_hi)[i] = hp;
    ((uint2*)g_lo)[i] = lp;
}

// issue cp.async for one K=32 chunk (4 tiles) into buffer (c & 1)
static __device__ __forceinline__ void issue_chunk(uint32_t sb, int tid,
                                                   int i0, int j0, int c) {
    uint32_t dst0 = sb + OFF_TILES + (c & 1) * BUF_B;
    #pragma unroll
    for (int it = 0; it < 8; it++) {
        int e    = it * 256 + tid;       // 0..2047 16B-ops
        int tile = e >> 9;               // 0..3
        int w    = e & 511;
        int r    = w >> 2, kc = w & 3;
        const __nv_bfloat16* src = (tile & 1) ? g_lo : g_hi;
        int row0 = (tile >> 1) ? j0 : i0;
        const void* g = src + (size_t)(row0 + r) * D + c * 32 + kc * 8;
        CP_ASYNC16(dst0 + tile * TILE_B + r * LDT + kc * 16, g);
    }
    CP_COMMIT();
}

// ---------------------------------------------------------------------------
// K2: Gram tile via mma.sync bf16 (3-product split), cp.async double-buffered
//     K=32 chunks, 2 CTAs/SM, register epilogue.
// ---------------------------------------------------------------------------
__global__ void __launch_bounds__(256, 2) k_dist() {
    extern __shared__ char smem[];
    uint32_t sb = smem_u32(smem);
    int tid = threadIdx.x;

    if (tid == 0) *(int*)(smem + OFF_PSN) = 0;

    // triangular block decode -> (bi, bj), bi <= bj
    int idx = blockIdx.x, bi = 0, rem = idx;
    while (rem >= NT - bi) { rem -= NT - bi; bi++; }
    int bj = bi + rem;
    int i0 = bi * 128, j0 = bj * 128;

    issue_chunk(sb, tid, i0, j0, 0);     // prologue

    float* magis = (float*)(smem + OFF_MAGI);
    float* magjs = (float*)(smem + OFF_MAGJ);
    int*   tis   = (int*)(smem + OFF_TI);
    int*   tjs   = (int*)(smem + OFF_TJ);
    float* rbuf  = (float*)(smem + OFF_RBUF);
    float* cbuf  = (float*)(smem + OFF_CBUF);

    if (tid < 128) {
        magis[tid] = g_mag[i0 + tid];
        magjs[tid] = g_mag[j0 + tid];
        tis[tid]   = g_t32[i0 + tid];
        tjs[tid]   = g_t32[j0 + tid];
        rbuf[tid] = 0.f; cbuf[tid] = 0.f;
    }

    int wid = tid >> 5, lane = tid & 31;
    int wm = wid & 1, wn = wid >> 1;

    float acc[4][4][4];
    #pragma unroll
    for (int mt = 0; mt < 4; mt++)
        #pragma unroll
        for (int nt = 0; nt < 4; nt++)
            #pragma unroll
            for (int q = 0; q < 4; q++) acc[mt][nt][q] = 0.f;

    uint32_t aRowOff = ((lane & 7) + ((lane >> 3) & 1) * 8) * LDT + (lane >> 4) * 16;
    uint32_t bRowOff = ((lane & 7) + (lane >> 4) * 8) * LDT + ((lane >> 3) & 1) * 16;

    #pragma unroll
    for (int c = 0; c < 4; c++) {
        if (c < 3) issue_chunk(sb, tid, i0, j0, c + 1);
        if (c < 3) { CP_WAIT(1); } else { CP_WAIT(0); }
        __syncthreads();                 // chunk c data visible to all

        uint32_t buf = sb + OFF_TILES + (c & 1) * BUF_B;
        uint32_t aHiBase = buf + 0 * TILE_B + wm * 64 * LDT + aRowOff;
        uint32_t aLoBase = buf + 1 * TILE_B + wm * 64 * LDT + aRowOff;
        uint32_t bHiBase = buf + 2 * TILE_B + wn * 32 * LDT + bRowOff;
        uint32_t bLoBase = buf + 3 * TILE_B + wn * 32 * LDT + bRowOff;

        #pragma unroll
        for (int ks = 0; ks < 2; ks++) {
            uint32_t ko = ks * 32;
            uint32_t bh[8], bl[8];
            LDSM4(bh[0], bh[1], bh[2], bh[3], bHiBase + ko);
            LDSM4(bh[4], bh[5], bh[6], bh[7], bHiBase + 16 * LDT + ko);
            LDSM4(bl[0], bl[1], bl[2], bl[3], bLoBase + ko);
            LDSM4(bl[4], bl[5], bl[6], bl[7], bLoBase + 16 * LDT + ko);
            #pragma unroll
            for (int mt = 0; mt < 4; mt++) {
                uint32_t ah[4], al[4];
                LDSM4(ah[0], ah[1], ah[2], ah[3], aHiBase + mt * 16 * LDT + ko);
                LDSM4(al[0], al[1], al[2], al[3], aLoBase + mt * 16 * LDT + ko);
                #pragma unroll
                for (int nt = 0; nt < 4; nt++) {
                    MMA_BF16(acc[mt][nt], ah[0], ah[1], ah[2], ah[3],
                             bh[nt * 2], bh[nt * 2 + 1]);
                    MMA_BF16(acc[mt][nt], ah[0], ah[1], ah[2], ah[3],
                             bl[nt * 2], bl[nt * 2 + 1]);
                    MMA_BF16(acc[mt][nt], al[0], al[1], al[2], al[3],
                             bh[nt * 2], bh[nt * 2 + 1]);
                }
            }
        }
        __syncthreads();                 // all LDSM reads done before overwrite
    }

    // --- register epilogue ---
    int qr = lane >> 2, qc2 = (lane & 3) * 2;
    float* psd = (float*)(smem + OFF_PSD);
    unsigned* psij = (unsigned*)(smem + OFF_PSIJ);
    int* psn = (int*)(smem + OFF_PSN);

    float magi_r[8]; int ti_r[8];
    #pragma unroll
    for (int mt = 0; mt < 4; mt++)
        #pragma unroll
        for (int h = 0; h < 2; h++) {
            int rl = wm * 64 + mt * 16 + qr + h * 8;
            magi_r[mt * 2 + h] = magis[rl];
            ti_r[mt * 2 + h]   = tis[rl];
        }

    float rowsum[8] = {0,0,0,0,0,0,0,0};
    float colsum[8] = {0,0,0,0,0,0,0,0};

    #pragma unroll
    for (int nt = 0; nt < 4; nt++) {
        int cl = wn * 32 + nt * 8 + qc2;
        float mj0 = magjs[cl], mj1 = magjs[cl + 1];
        int   tj0 = tjs[cl],   tj1 = tjs[cl + 1];
        #pragma unroll
        for (int mt = 0; mt < 4; mt++) {
            #pragma unroll
            for (int h = 0; h < 2; h++) {
                int ri = mt * 2 + h;
                int rl = wm * 64 + mt * 16 + qr + h * 8;
                #pragma unroll
                for (int v = 0; v < 2; v++) {
                    float sim = acc[mt][nt][h * 2 + v];
                    float mj  = v ? mj1 : mj0;
                    int   tj  = v ? tj1 : tj0;
                    float d2 = magi_r[ri] + mj - 2.f * sim;
                    float dist = d2 > 0.f ? sqrt_approx(d2) : 0.f;
                    if (ti_r[ri] != tj) {
                        float e = __expf(1.0f - dist);
                        rowsum[ri] += e;
                        colsum[nt * 2 + v] += e;
                    } else {
                        int gi = i0 + rl, gj = j0 + cl + v;
                        if (gi < gj) {
                            int slot = atomicAdd(psn, 1);
                            if (slot < PB) {
                                psd[slot]  = dist;
                                psij[slot] = ((unsigned)gi << 12) | (unsigned)gj;
                            }
                        }
                    }
                }
            }
        }
    }

    #pragma unroll
    for (int k = 0; k < 8; k++) {
        rowsum[k] += __shfl_xor_sync(0xffffffff, rowsum[k], 1);
        rowsum[k] += __shfl_xor_sync(0xffffffff, rowsum[k], 2);
        colsum[k] += __shfl_xor_sync(0xffffffff, colsum[k], 4);
        colsum[k] += __shfl_xor_sync(0xffffffff, colsum[k], 8);
        colsum[k] += __shfl_xor_sync(0xffffffff, colsum[k], 16);
    }
    if ((lane & 3) == 0) {
        #pragma unroll
        for (int mt = 0; mt < 4; mt++)
            #pragma unroll
            for (int h = 0; h < 2; h++)
                atomicAdd(&rbuf[wm * 64 + mt * 16 + qr + h * 8],
                          rowsum[mt * 2 + h]);
    }
    if (lane < 4) {
        #pragma unroll
        for (int nt = 0; nt < 4; nt++)
            #pragma unroll
            for (int v = 0; v < 2; v++)
                atomicAdd(&cbuf[wn * 32 + nt * 8 + lane * 2 + v],
                          colsum[nt * 2 + v]);
    }
    __syncthreads();

    if (tid < 128) {
        atomicAdd(&g_rowneg[i0 + tid], rbuf[tid]);
        if (bi != bj) atomicAdd(&g_rowneg[j0 + tid], cbuf[tid]);
    }

    // flush positive pairs: one global atomic + coalesced copy
    if (tid == 0) {
        int n = *psn; if (n > PB) n = PB;
        *(int*)(smem + OFF_PSBASE) = atomicAdd(&g_npairs, n);
    }
    __syncthreads();
    int n = *psn; if (n > PB) n = PB;
    int base = *(int*)(smem + OFF_PSBASE);
    for (int s = tid; s < n; s += 256) {
        g_pair_d[base + s]  = psd[s];
        g_pair_ij[base + s] = psij[s];
    }
}

// ---------------------------------------------------------------------------
// K3: hinge^2 over compacted positive pairs
// ---------------------------------------------------------------------------
__global__ void __launch_bounds__(256) k_loss() {
    int np = g_npairs;
    float sum = 0.f;
    for (int p = blockIdx.x * 256 + threadIdx.x; p < np; p += gridDim.x * 256) {
        float dist  = g_pair_d[p];
        unsigned ij = g_pair_ij[p];
        int i = (int)(ij >> 12), j = (int)(ij & 4095u);
        float l = logf(g_rowneg[i] + g_rowneg[j]) + dist;
        if (l > 0.f) sum += l * l;
    }
    #pragma unroll
    for (int off = 16; off; off >>= 1) sum += __shfl_xor_sync(0xffffffff, sum, off);
    __shared__ float ws[8];
    if ((threadIdx.x & 31) == 0) ws[threadIdx.x >> 5] = sum;
    __syncthreads();
    if (threadIdx.x < 8) {
        float s = ws[threadIdx.x];
        #pragma unroll
        for (int off = 4; off; off >>= 1) s += __shfl_xor_sync(0xff, s, off);
        if (threadIdx.x == 0 && s != 0.f) atomicAdd(&g_loss, (double)s);
    }
}

// ---------------------------------------------------------------------------
__global__ void k_final(float* __restrict__ out) {
    __shared__ long long cnt[NCLS];
    int t = threadIdx.x;
    long long n = (long long)g_hist[t];
    cnt[t] = n * (n - 1) / 2;
    __syncthreads();
    if (t == 0) {
        long long total = 0;
        #pragma unroll
        for (int c = 0; c < NCLS; c++) total += cnt[c];
        out[0] = (float)(g_loss / (2.0 * (double)total));
    }
}

// ---------------------------------------------------------------------------
extern "C" void kernel_launch(void* const* d_in, const int* in_sizes, int n_in,
                              void* d_out, int out_size) {
    const float* X   = (const float*)d_in[0];
    const int*   T   = (const int*)d_in[1];
    float*       out = (float*)d_out;

    cudaFuncSetAttribute(k_dist, cudaFuncAttributeMaxDynamicSharedMemorySize,
                         SMEM_TOTAL);

    k_init<<<16, 256>>>();
    k_mag<<<B / 8, 256>>>(X, T);
    k_split<<<(B * D / 4) / 256, 256>>>(X);
    k_dist<<<NT * (NT + 1) / 2, 256, SMEM_TOTAL>>>();
    k_loss<<<256, 256>>>();
    k_final<<<1, NCLS>>>(out);
}